// round 16
// baseline (speedup 1.0000x reference)
#include <cuda_runtime.h>

// Triplet margin loss, B=65536 rows, D=256 floats per row.
// R16 probe (last untested load-path variant): 256-bit NON-COHERENT loads
// (ld.global.nc.v8.f32 -> LDG.E.256.CONSTANT). Inputs are read-only and
// disjoint, so the read-only descriptor path is legal. Everything else is
// the converged R12 config:
//   - one row = 1024B = 32 lanes x 32B -> 3 wide loads per warp
//   - 256-thread blocks (8 warps, 8192 blocks)
//   - warp shuffle reduce; serial thread-0 block sum
//   - fence-free packed-atomic finalize (count + fixed-point sum in ONE
//     64-bit atomicAdd; no __threadfence -> no per-CTA CCTL.IVALL)

static constexpr int B = 65536;
static constexpr int D = 256;            // floats per row
static constexpr int WARPS_PER_BLOCK = 8;
static constexpr int THREADS = WARPS_PER_BLOCK * 32;
static constexpr int BLOCKS = B / WARPS_PER_BLOCK;   // 8192

static constexpr int COUNT_SHIFT = 50;
// Max sum: ~1.3e11 * 256 = 3.4e13 < 2^50. Count max 8192 fits in [50:63].

// Zero at module load; last block resets it each launch (deterministic replays).
__device__ unsigned long long g_acc = 0ull;

// 256-bit non-coherent (read-only path) global load on sm_100+/sm_103a.
__device__ __forceinline__ void ldg256nc(float r[8], const float* ptr) {
    asm("ld.global.nc.v8.f32 {%0,%1,%2,%3,%4,%5,%6,%7}, [%8];"
        : "=f"(r[0]), "=f"(r[1]), "=f"(r[2]), "=f"(r[3]),
          "=f"(r[4]), "=f"(r[5]), "=f"(r[6]), "=f"(r[7])
        : "l"(ptr));
}

__global__ void __launch_bounds__(THREADS)
triplet_loss_kernel(const float* __restrict__ a,
                    const float* __restrict__ p,
                    const float* __restrict__ n,
                    float* __restrict__ out,
                    float inv_b) {
    const int warp_in_block = threadIdx.x >> 5;
    const int lane = threadIdx.x & 31;
    const long long row = (long long)blockIdx.x * WARPS_PER_BLOCK + warp_in_block;
    const long long off = row * D + lane * 8;

    // Front-batch 3 x 256-bit read-only loads (96B per thread in flight).
    float A[8], P[8], N[8];
    ldg256nc(A, a + off);
    ldg256nc(P, p + off);
    ldg256nc(N, n + off);

    float dap2 = 0.f, dan2 = 0.f, dpn2 = 0.f;
    #pragma unroll
    for (int i = 0; i < 8; i++) {
        float d1 = A[i] - P[i]; dap2 += d1 * d1;
        float d2 = A[i] - N[i]; dan2 += d2 * d2;
        float d3 = P[i] - N[i]; dpn2 += d3 * d3;
    }

    // Warp reduce the three partial sums.
    #pragma unroll
    for (int off2 = 16; off2 > 0; off2 >>= 1) {
        dap2 += __shfl_xor_sync(0xFFFFFFFFu, dap2, off2);
        dan2 += __shfl_xor_sync(0xFFFFFFFFu, dan2, off2);
        dpn2 += __shfl_xor_sync(0xFFFFFFFFu, dpn2, off2);
    }

    __shared__ float warp_loss[WARPS_PER_BLOCK];
    if (lane == 0) {
        float dap = sqrtf(dap2);
        float dan = sqrtf(dan2);
        float dpn = sqrtf(dpn2);
        float margin_sim    = 1.0f + 2.0f / (expf(4.0f * dap) + 1e-6f);
        float margin_dissim = 1.0f + 2.0f / (expf(4.0f - 4.0f * dan) + 1e-6f);
        float loss = dap - 0.5f * (dan + dpn) + margin_sim + margin_dissim;
        warp_loss[warp_in_block] = loss;
    }
    __syncthreads();

    if (threadIdx.x == 0) {
        float s = 0.f;
        #pragma unroll
        for (int i = 0; i < WARPS_PER_BLOCK; i++) s += warp_loss[i];

        // Fixed-point contribution: strictly positive (~1.6e7 per block).
        unsigned long long fixed = __float2ull_rn(s * 256.0f);
        unsigned long long contrib = (1ull << COUNT_SHIFT) + fixed;
        unsigned long long prev = atomicAdd(&g_acc, contrib);

        if ((prev >> COUNT_SHIFT) == (unsigned long long)(BLOCKS - 1)) {
            // Last arrival: prev+contrib holds the full count and full sum.
            unsigned long long total_fixed =
                (prev + contrib) & ((1ull << COUNT_SHIFT) - 1ull);
            out[0] = (float)((double)total_fixed * (1.0 / 256.0)) * inv_b;
            // Reset for the next graph replay (no concurrent writers remain).
            atomicExch(&g_acc, 0ull);
        }
    }
}

extern "C" void kernel_launch(void* const* d_in, const int* in_sizes, int n_in,
                              void* d_out, int out_size) {
    const float* a = (const float*)d_in[0];
    const float* p = (const float*)d_in[1];
    const float* n = (const float*)d_in[2];
    float* out = (float*)d_out;

    triplet_loss_kernel<<<BLOCKS, THREADS>>>(a, p, n, out, 1.0f / (float)B);
}

// round 17
// speedup vs baseline: 1.0095x; 1.0095x over previous
#include <cuda_runtime.h>

// Triplet margin loss, B=65536 rows, D=256 floats per row.
// R17 probe (final load-path bit): 256-bit streaming loads WITH L2 256B
// prefetch-granularity hint (ld.global.cs.L2::256B.v8.f32). Each warp's v8
// load covers 1024 contiguous bytes; the hint asks the memory system to
// fetch in 256B granules -> fewer, larger DRAM bursts. Pure hint, no
// semantic change. Everything else is the converged R12 config:
//   - one row = 1024B = 32 lanes x 32B -> 3 wide loads per warp
//   - 256-thread blocks (8 warps, 8192 blocks)
//   - warp shuffle reduce; serial thread-0 block sum
//   - fence-free packed-atomic finalize (count + fixed-point sum in ONE
//     64-bit atomicAdd; no __threadfence -> no per-CTA CCTL.IVALL)

static constexpr int B = 65536;
static constexpr int D = 256;            // floats per row
static constexpr int WARPS_PER_BLOCK = 8;
static constexpr int THREADS = WARPS_PER_BLOCK * 32;
static constexpr int BLOCKS = B / WARPS_PER_BLOCK;   // 8192

static constexpr int COUNT_SHIFT = 50;
// Max sum: ~1.3e11 * 256 = 3.4e13 < 2^50. Count max 8192 fits in [50:63].

// Zero at module load; last block resets it each launch (deterministic replays).
__device__ unsigned long long g_acc = 0ull;

// 256-bit streaming global load with 256B L2 fetch-granularity hint.
__device__ __forceinline__ void ldg256cs_l2(float r[8], const float* ptr) {
    asm("ld.global.cs.L2::256B.v8.f32 {%0,%1,%2,%3,%4,%5,%6,%7}, [%8];"
        : "=f"(r[0]), "=f"(r[1]), "=f"(r[2]), "=f"(r[3]),
          "=f"(r[4]), "=f"(r[5]), "=f"(r[6]), "=f"(r[7])
        : "l"(ptr));
}

__global__ void __launch_bounds__(THREADS)
triplet_loss_kernel(const float* __restrict__ a,
                    const float* __restrict__ p,
                    const float* __restrict__ n,
                    float* __restrict__ out,
                    float inv_b) {
    const int warp_in_block = threadIdx.x >> 5;
    const int lane = threadIdx.x & 31;
    const long long row = (long long)blockIdx.x * WARPS_PER_BLOCK + warp_in_block;
    const long long off = row * D + lane * 8;

    // Front-batch 3 x 256-bit streaming loads (96B per thread in flight).
    float A[8], P[8], N[8];
    ldg256cs_l2(A, a + off);
    ldg256cs_l2(P, p + off);
    ldg256cs_l2(N, n + off);

    float dap2 = 0.f, dan2 = 0.f, dpn2 = 0.f;
    #pragma unroll
    for (int i = 0; i < 8; i++) {
        float d1 = A[i] - P[i]; dap2 += d1 * d1;
        float d2 = A[i] - N[i]; dan2 += d2 * d2;
        float d3 = P[i] - N[i]; dpn2 += d3 * d3;
    }

    // Warp reduce the three partial sums.
    #pragma unroll
    for (int off2 = 16; off2 > 0; off2 >>= 1) {
        dap2 += __shfl_xor_sync(0xFFFFFFFFu, dap2, off2);
        dan2 += __shfl_xor_sync(0xFFFFFFFFu, dan2, off2);
        dpn2 += __shfl_xor_sync(0xFFFFFFFFu, dpn2, off2);
    }

    __shared__ float warp_loss[WARPS_PER_BLOCK];
    if (lane == 0) {
        float dap = sqrtf(dap2);
        float dan = sqrtf(dan2);
        float dpn = sqrtf(dpn2);
        float margin_sim    = 1.0f + 2.0f / (expf(4.0f * dap) + 1e-6f);
        float margin_dissim = 1.0f + 2.0f / (expf(4.0f - 4.0f * dan) + 1e-6f);
        float loss = dap - 0.5f * (dan + dpn) + margin_sim + margin_dissim;
        warp_loss[warp_in_block] = loss;
    }
    __syncthreads();

    if (threadIdx.x == 0) {
        float s = 0.f;
        #pragma unroll
        for (int i = 0; i < WARPS_PER_BLOCK; i++) s += warp_loss[i];

        // Fixed-point contribution: strictly positive (~1.6e7 per block).
        unsigned long long fixed = __float2ull_rn(s * 256.0f);
        unsigned long long contrib = (1ull << COUNT_SHIFT) + fixed;
        unsigned long long prev = atomicAdd(&g_acc, contrib);

        if ((prev >> COUNT_SHIFT) == (unsigned long long)(BLOCKS - 1)) {
            // Last arrival: prev+contrib holds the full count and full sum.
            unsigned long long total_fixed =
                (prev + contrib) & ((1ull << COUNT_SHIFT) - 1ull);
            out[0] = (float)((double)total_fixed * (1.0 / 256.0)) * inv_b;
            // Reset for the next graph replay (no concurrent writers remain).
            atomicExch(&g_acc, 0ull);
        }
    }
}

extern "C" void kernel_launch(void* const* d_in, const int* in_sizes, int n_in,
                              void* d_out, int out_size) {
    const float* a = (const float*)d_in[0];
    const float* p = (const float*)d_in[1];
    const float* n = (const float*)d_in[2];
    float* out = (float*)d_out;

    triplet_loss_kernel<<<BLOCKS, THREADS>>>(a, p, n, out, 1.0f / (float)B);
}